// round 16
// baseline (speedup 1.0000x reference)
#include <cuda_runtime.h>
#include <cuda_fp16.h>
#include <math.h>
#include <stdint.h>

#define BB 4
#define TT 2048
#define DD 512
#define HH 2048
#define VV 256
#define NTOK (BB*TT)   // 8192
#define CS 64
#define NCH (TT/CS)

// ---------------- scratch ----------------
__device__ __align__(128) float g_h[NTOK*DD];
__device__ __align__(128) float g_s1[NTOK*DD];
__device__ __align__(128) float g_partA[BB*NCH*DD];
__device__ __align__(128) float g_partB[BB*NCH*DD];
__device__ __align__(128) __half g_s2[NTOK*DD];                 // LN out, fp16
__device__ __align__(128) __half g_act[(size_t)NTOK*HH];        // GELU out, fp16
__device__ __align__(128) __half g_hq[NTOK*DD];                 // final h, fp16
__device__ __align__(128) __half g_w1h[3*DD*HH];
__device__ __align__(128) __half g_w2h[3*DD*HH];
__device__ __align__(128) __half g_eth[DD*VV];                  // embed^T hi
__device__ __align__(128) __half g_etl[DD*VV];                  // embed^T lo

__device__ __forceinline__ float softplus_lambda(float kv) {
    float sp = (kv > 0.f) ? (kv + log1pf(expf(-kv))) : log1pf(expf(kv));
    return expf(-sp);
}

// ---------------- weight prepass (both W1, W2 single fp16) -----------------
__global__ void split_weights_kernel(const float* __restrict__ W1, const float* __restrict__ W2) {
    size_t i = (size_t)blockIdx.x * blockDim.x + threadIdx.x;
    g_w1h[i] = __float2half(W1[i]);
    g_w2h[i] = __float2half(W2[i]);
}

// ---------------- embed^T split prepass: E[VV][DD] -> embT[DD][VV] hi/lo ---
__global__ void embedT_split_kernel(const float* __restrict__ E) {
    __shared__ float t[32][33];
    int v0 = blockIdx.x * 32, d0 = blockIdx.y * 32;
    #pragma unroll
    for (int i = threadIdx.y; i < 32; i += 8)
        t[i][threadIdx.x] = E[(size_t)(v0 + i) * DD + d0 + threadIdx.x];
    __syncthreads();
    #pragma unroll
    for (int i = threadIdx.y; i < 32; i += 8) {
        float val = t[threadIdx.x][i];
        size_t idx = (size_t)(d0 + i) * VV + v0 + threadIdx.x;
        __half hh = __float2half(val);
        g_eth[idx] = hh;
        g_etl[idx] = __float2half(val - __half2float(hh));
    }
}

// ---------------- fused embed gather + tanh(cumprod) (warp per token) ------
__global__ void embed_cumprod_kernel(const int* __restrict__ x, const float* __restrict__ embed) {
    int w = threadIdx.x >> 5;
    int lane = threadIdx.x & 31;
    int tok = blockIdx.x * 8 + w;
    const float* src = embed + (size_t)x[tok] * DD;
    size_t base = (size_t)tok * DD + lane * 16;
    float v[16];
    #pragma unroll
    for (int j = 0; j < 4; j++)
        *(float4*)&v[j * 4] = *(const float4*)(src + lane * 16 + j * 4);
    float c[16];
    float run = 1.f;
    #pragma unroll
    for (int j = 0; j < 16; j++) {
        run *= v[j];
        c[j] = run;
    }
    float incl = run;
    #pragma unroll
    for (int off = 1; off < 32; off <<= 1) {
        float p = __shfl_up_sync(0xffffffffu, incl, off);
        if (lane >= off) incl *= p;
    }
    float pre = __shfl_up_sync(0xffffffffu, incl, 1);
    if (lane == 0) pre = 1.f;
    #pragma unroll
    for (int j = 0; j < 4; j++) {
        *(float4*)&g_h[base + j * 4] = *(const float4*)&v[j * 4];
        float4 o;
        o.x = tanhf(pre * c[j * 4 + 0]);
        o.y = tanhf(pre * c[j * 4 + 1]);
        o.z = tanhf(pre * c[j * 4 + 2]);
        o.w = tanhf(pre * c[j * 4 + 3]);
        *(float4*)&g_s1[base + j * 4] = o;
    }
}

// ============= boundary scan (d-split: grid z=2, 256 threads) ==============
__global__ void boundA_kernel() {
    int b = blockIdx.x, ch = blockIdx.y;
    int d = blockIdx.z * 256 + threadIdx.x;
    size_t base = ((size_t)b * TT + ch * CS) * DD + d;
    float s = 0.f;
    #pragma unroll 8
    for (int i = 0; i < CS; i++) s += g_s1[base + (size_t)i * DD];
    g_partA[((size_t)b * NCH + ch) * DD + d] = s;
}

__global__ void boundB_kernel() {
    int b = blockIdx.x, d = threadIdx.x;
    float c = 0.f;
    for (int ch = 0; ch < NCH; ch++) {
        size_t idx = ((size_t)b * NCH + ch) * DD + d;
        float v = g_partA[idx];
        g_partA[idx] = c;
        c += v;
    }
}

__global__ void boundC_kernel() {
    int b = blockIdx.x, ch = blockIdx.y;
    int d = blockIdx.z * 256 + threadIdx.x;
    size_t base = ((size_t)b * TT + ch * CS) * DD + d;
    float acc = g_partA[((size_t)b * NCH + ch) * DD + d];
    #pragma unroll 4
    for (int i = 0; i < CS; i++) {
        size_t idx = base + (size_t)i * DD;
        acc += g_s1[idx];
        g_h[idx] = g_h[idx] * (1.0f + acc);
    }
}

// ============= per-layer scans =============================================
__global__ void scanA_kernel(const float* __restrict__ kpar, int l) {
    int b = blockIdx.x, ch = blockIdx.y;
    int d = blockIdx.z * 256 + threadIdx.x;
    float lam = softplus_lambda(kpar[l]);
    size_t base = ((size_t)b * TT + ch * CS) * DD + d;
    float s = 0.f, loc = 0.f;
    #pragma unroll 4
    for (int i = 0; i < CS; i++) {
        float v = g_h[base + (size_t)i * DD];
        s += v;
        loc = v + lam * loc;
    }
    size_t pidx = ((size_t)b * NCH + ch) * DD + d;
    g_partA[pidx] = s;
    g_partB[pidx] = loc;
}

__global__ void scanB_kernel(const float* __restrict__ kpar, int l) {
    int b = blockIdx.x, d = threadIdx.x;
    float lam = softplus_lambda(kpar[l]);
    float lamCS = powf(lam, (float)CS);
    float c1 = 0.f, c2 = 0.f;
    for (int ch = 0; ch < NCH; ch++) {
        size_t idx = ((size_t)b * NCH + ch) * DD + d;
        float a = g_partA[idx];
        float v = g_partB[idx];
        g_partA[idx] = c1;
        g_partB[idx] = c2;
        c1 += a;
        c2 = v + lamCS * c2;
    }
}

// ======== fused mag + decay-ctx + layernorm -> fp16 s2 =====================
#define MLN_SMEM ((CS*DD + 3*CS*17 + 3*CS) * 4)

__global__ void __launch_bounds__(DD, 1) mag_ln_kernel(const float* __restrict__ kpar, int l,
                                                       const float* __restrict__ gamma,
                                                       const float* __restrict__ beta) {
    extern __shared__ float sm[];
    float* sS  = sm;
    float* aM  = sS + CS * DD;
    float* a1  = aM + CS * 17;
    float* a2  = a1 + CS * 17;
    float* smu = a2 + CS * 17;
    float* srs = smu + CS;
    float* smg = srs + CS;

    int b = blockIdx.x, ch = blockIdx.y;
    int d = threadIdx.x;
    int lane = d & 31, wd = d >> 5;
    int t0 = ch * CS;
    size_t base = ((size_t)b * TT + t0) * DD + d;
    float lam = softplus_lambda(kpar[l]);
    float acc = g_partA[((size_t)b * NCH + ch) * DD + d];
    float S = g_partB[((size_t)b * NCH + ch) * DD + d];
    float hp = (t0 > 0) ? g_h[base - DD] : 0.f;

    #pragma unroll 4
    for (int i = 0; i < CS; i++) {
        float v = g_h[base + (size_t)i * DD];
        acc += v;
        float diff = acc - hp;
        float sq = diff * diff;
        S = v + lam * S;
        sS[i * DD + d] = S;
        float u1 = fabsf(S);
        float u2 = S * S;
        #pragma unroll
        for (int o = 16; o; o >>= 1) {
            sq += __shfl_down_sync(0xffffffffu, sq, o);
            u1 += __shfl_down_sync(0xffffffffu, u1, o);
            u2 += __shfl_down_sync(0xffffffffu, u2, o);
        }
        if (lane == 0) {
            aM[i * 17 + wd] = sq;
            a1[i * 17 + wd] = u1;
            a2[i * 17 + wd] = u2;
        }
        hp = v;
    }
    __syncthreads();
    if (d < CS) {
        float sm_ = 0.f, s1_ = 0.f, s2_ = 0.f;
        #pragma unroll
        for (int w = 0; w < 16; w++) {
            sm_ += aM[d * 17 + w];
            s1_ += a1[d * 17 + w];
            s2_ += a2[d * 17 + w];
        }
        float mag = sqrtf(sm_);
        float mu = mag * s1_ * (1.0f / DD);
        float ex2 = mag * mag * s2_ * (1.0f / DD);
        float var = ex2 - mu * mu;
        smu[d] = mu;
        srs[d] = rsqrtf(var + 1e-3f);
        smg[d] = mag;
    }
    __syncthreads();
    float gm = gamma[d], bt = beta[d];
    #pragma unroll 4
    for (int i = 0; i < CS; i++) {
        float ctx = smg[i] * fabsf(sS[i * DD + d]);
        float y = (ctx - smu[i]) * srs[i] * gm + bt;
        g_s2[base + (size_t)i * DD] = __float2half(y);
    }
}

// ============ fp16 tensor-core GEMM, K64 stages (4 x K16 sub-tiles) ========
// 128x128 block tile, 8 warps (2m x 4n), half-staged registers (2 x K32),
// double-buffered, TERMS-dependent smem layout.
// EPI 0: bias+GELU -> fp16 Ch.  EPI 1: bias+accum into Cf (+opt fp16 Ch).
// EPI 2: plain store to Cf.
#define AROWB 48
#define A_TILE_B (128*AROWB)           // 6144 per K16
#define BROWB 272
#define B_TILE_B (16*BROWB)            // 4352 per K16
#define A_ST (4*A_TILE_B)              // 24576 per K64 stage
#define SMA (2*A_ST)                   // 49152
#define GSMEM1 (SMA + 2*4*1*B_TILE_B)  // 83968  (TERMS=1)
#define GSMEM2 (SMA + 2*4*2*B_TILE_B)  // 118784 (TERMS=2)

#define LDSM4(r0,r1,r2,r3,addr) \
    asm volatile("ldmatrix.sync.aligned.m8n8.x4.shared.b16 {%0,%1,%2,%3},[%4];" \
                 : "=r"(r0),"=r"(r1),"=r"(r2),"=r"(r3) : "r"(addr))
#define LDSM4T(r0,r1,r2,r3,addr) \
    asm volatile("ldmatrix.sync.aligned.m8n8.x4.trans.shared.b16 {%0,%1,%2,%3},[%4];" \
                 : "=r"(r0),"=r"(r1),"=r"(r2),"=r"(r3) : "r"(addr))
#define MMA_F16(c,a,b0,b1) \
    asm volatile("mma.sync.aligned.m16n8k16.row.col.f32.f16.f16.f32 " \
                 "{%0,%1,%2,%3},{%4,%5,%6,%7},{%8,%9},{%0,%1,%2,%3};" \
                 : "+f"(c[0]),"+f"(c[1]),"+f"(c[2]),"+f"(c[3]) \
                 : "r"(a[0]),"r"(a[1]),"r"(a[2]),"r"(a[3]),"r"(b0),"r"(b1))

struct HalfRegs { uint4 ah[2], bh[2], bl[2]; };

// load one K32 half (2 x K16 sub-tiles) starting at global k = k0
template <int TERMS>
__device__ __forceinline__ void ldg_half(const __half* __restrict__ A,
                                         const __half* __restrict__ Bh,
                                         const __half* __restrict__ Bl,
                                         int bm, int bn, int k0, int K, int N,
                                         int tid, HalfRegs& r) {
    int arow = tid >> 1, aseg = tid & 1;
    int k = tid >> 4, ng = tid & 15;
    #pragma unroll
    for (int j = 0; j < 2; j++) {
        int ks = k0 + j * 16;
        r.ah[j] = *(const uint4*)(A + (size_t)(bm + arow) * K + ks + aseg * 8);
        size_t bbase = (size_t)(ks + k) * N + bn + ng * 8;
        r.bh[j] = *(const uint4*)(Bh + bbase);
        if (TERMS == 2) r.bl[j] = *(const uint4*)(Bl + bbase);
    }
}

// store one K32 half into stage buffer p, half index h (subtiles 2h, 2h+1)
template <int TERMS>
__device__ __forceinline__ void sts_half(char* sbase, int p, int h, int tid, const HalfRegs& r) {
    const int BSUBT = TERMS * B_TILE_B;
    const int B_ST = 4 * BSUBT;
    int arow = tid >> 1, aseg = tid & 1;
    int k = tid >> 4, ng = tid & 15;
    #pragma unroll
    for (int j = 0; j < 2; j++) {
        int s = 2 * h + j;
        *(uint4*)(sbase + p * A_ST + s * A_TILE_B + arow * AROWB + aseg * 16) = r.ah[j];
        char* Bp = sbase + SMA + p * B_ST + s * BSUBT;
        *(uint4*)(Bp + k * BROWB + ng * 16) = r.bh[j];
        if (TERMS == 2) *(uint4*)(Bp + B_TILE_B + k * BROWB + ng * 16) = r.bl[j];
    }
}

__device__ __forceinline__ float gelu_exact(float c) {
    return 0.5f * c * (1.0f + erff(c * 0.70710678118654752f));
}

template <int EPI, int TERMS>
__device__ __forceinline__ void gemm_f16(const __half* __restrict__ A,
                                         const __half* __restrict__ Bh,
                                         const __half* __restrict__ Bl,
                                         const float* __restrict__ bias,
                                         float* __restrict__ Cf,
                                         __half* __restrict__ Ch,
                                         int M, int N, int K, int emit_half) {
    extern __shared__ char smc[];
    const int BSUBT = TERMS * B_TILE_B;
    const int B_ST = 4 * BSUBT;
    const int bm = blockIdx.y * 128;
    const int bn = blockIdx.x * 128;
    const int tid = threadIdx.x;
    const int lane = tid & 31;
    const int wid = tid >> 5;
    const int wm = wid >> 2, wn = wid & 3;
    const int g = lane >> 2, kq = lane & 3;
    const int lrow = lane & 7, lmat = lane >> 3;

    const uint32_t smem_u32 = (uint32_t)__cvta_generic_to_shared(smc);
    const uint32_t aoff = smem_u32 + (uint32_t)((wm * 64 + (lmat & 1) * 8 + lrow) * AROWB + (lmat >> 1) * 16);
    const uint32_t boff = smem_u32 + SMA +
                          (uint32_t)(((lmat & 1) * 8 + lrow) * BROWB + (wn * 32 + (lmat >> 1) * 8) * 2);

    float acc[4][4][4];
    #pragma unroll
    for (int mt = 0; mt < 4; mt++)
        #pragma unroll
        for (int nt = 0; nt < 4; nt++)
            #pragma unroll
            for (int r = 0; r < 4; r++) acc[mt][nt][r] = 0.f;

    const int KT = K >> 6;             // K64 stages
    HalfRegs hr;
    ldg_half<TERMS>(A, Bh, Bl, bm, bn, 0, K, N, tid, hr);
    sts_half<TERMS>(smc, 0, 0, tid, hr);
    ldg_half<TERMS>(A, Bh, Bl, bm, bn, 32, K, N, tid, hr);
    sts_half<TERMS>(smc, 0, 1, tid, hr);
    __syncthreads();

    for (int kt = 0; kt < KT; kt++) {
        const int p = kt & 1;
        const bool more = (kt + 1 < KT);
        const int nk = (kt + 1) << 6;
        if (more) ldg_half<TERMS>(A, Bh, Bl, bm, bn, nk, K, N, tid, hr);

        #pragma unroll
        for (int half = 0; half < 2; half++) {
            #pragma unroll
            for (int sj = 0; sj < 2; sj++) {
                const int s = 2 * half + sj;
                const uint32_t aB = aoff + p * A_ST + s * A_TILE_B;
                const uint32_t bB = boff + p * B_ST + s * BSUBT;
                uint32_t aH[4][4];
                #pragma unroll
                for (int mt = 0; mt < 4; mt++)
                    LDSM4(aH[mt][0], aH[mt][1], aH[mt][2], aH[mt][3], aB + mt * (16 * AROWB));
                #pragma unroll
                for (int ntp = 0; ntp < 2; ntp++) {
                    uint32_t bh[4];
                    LDSM4T(bh[0], bh[1], bh[2], bh[3], bB + ntp * 32);
                    if (TERMS == 2) {
                        uint32_t bl[4];
                        LDSM4T(bl[0], bl[1], bl[2], bl[3], bB + ntp * 32 + B_TILE_B);
                        #pragma unroll
                        for (int w = 0; w < 2; w++) {
                            const int nt = 2 * ntp + w;
                            #pragma unroll
                            for (int mt = 0; mt < 4; mt++) {
                                MMA_F16(acc[mt][nt], aH[mt], bl[2 * w], bl[2 * w + 1]);
                                MMA_F16(acc[mt][nt], aH[mt], bh[2 * w], bh[2 * w + 1]);
                            }
                        }
                    } else {
                        #pragma unroll
                        for (int w = 0; w < 2; w++) {
                            const int nt = 2 * ntp + w;
                            #pragma unroll
                            for (int mt = 0; mt < 4; mt++)
                                MMA_F16(acc[mt][nt], aH[mt], bh[2 * w], bh[2 * w + 1]);
                        }
                    }
                }
            }
            // after first compute-half: commit staged half0 to p^1, load half1
            if (more && half == 0) {
                sts_half<TERMS>(smc, p ^ 1, 0, tid, hr);
                ldg_half<TERMS>(A, Bh, Bl, bm, bn, nk + 32, K, N, tid, hr);
            }
        }
        if (more) sts_half<TERMS>(smc, p ^ 1, 1, tid, hr);
        __syncthreads();
    }

    // epilogue
    #pragma unroll
    for (int mt = 0; mt < 4; mt++) {
        const int m0 = bm + wm * 64 + mt * 16 + g;
        #pragma unroll
        for (int nt = 0; nt < 4; nt++) {
            const int n0 = bn + wn * 32 + nt * 8 + kq * 2;
            const float b0 = (EPI == 2) ? 0.f : bias[n0];
            const float b1 = (EPI == 2) ? 0.f : bias[n0 + 1];
            if (EPI == 0) {
                float v0 = gelu_exact(acc[mt][nt][0] + b0);
                float v1 = gelu_exact(acc[mt][nt][1] + b1);
                float v2 = gelu_exact(acc[mt][nt][2] + b0);
                float v3 = gelu_exact(acc[mt][nt][3] + b1);
                __half2 p01 = __floats2half2_rn(v0, v1);
                __half2 p23 = __floats2half2_rn(v2, v3);
                size_t i0 = ((size_t)m0 * N + n0) >> 1;
                size_t i1 = ((size_t)(m0 + 8) * N + n0) >> 1;
                ((__half2*)Ch)[i0] = p01;
                ((__half2*)Ch)[i1] = p23;
            } else if (EPI == 1) {
                float2* p0 = (float2*)&Cf[(size_t)m0 * N + n0];
                float2* p1 = (float2*)&Cf[(size_t)(m0 + 8) * N + n0];
                float2 o0 = *p0, o1 = *p1;
                o0.x += acc[mt][nt][0] + b0;
                o0.y += acc[mt][nt][1] + b1;
                o1.x += acc[mt][nt][2] + b0;
                o1.y += acc[mt][nt][3] + b1;
                *p0 = o0;
                *p1 = o1;
                if (emit_half) {
                    size_t i0 = ((size_t)m0 * N + n0) >> 1;
                    size_t i1 = ((size_t)(m0 + 8) * N + n0) >> 1;
                    ((__half2*)Ch)[i0] = __floats2half2_rn(o0.x, o0.y);
                    ((__half2*)Ch)[i1] = __floats2half2_rn(o1.x, o1.y);
                }
            } else {
                *(float2*)&Cf[(size_t)m0 * N + n0] = make_float2(acc[mt][nt][0], acc[mt][nt][1]);
                *(float2*)&Cf[(size_t)(m0 + 8) * N + n0] = make_float2(acc[mt][nt][2], acc[mt][nt][3]);
            }
        }
    }
}

__global__ void __launch_bounds__(256, 2) gemm1_f16(const float* __restrict__ b1, int l) {
    gemm_f16<0, 1>(g_s2, g_w1h + (size_t)l * DD * HH, nullptr,
                   b1, nullptr, g_act, NTOK, HH, DD, 0);
}
__global__ void __launch_bounds__(256, 2) gemm2_f16(const float* __restrict__ b2, int l) {
    gemm_f16<1, 1>(g_act, g_w2h + (size_t)l * DD * HH, nullptr,
                   b2, g_h, g_hq, NTOK, DD, HH, l == 2 ? 1 : 0);
}
__global__ void __launch_bounds__(256, 1) gemm_out_f16(float* __restrict__ out) {
    gemm_f16<2, 2>(g_hq, g_eth, g_etl, nullptr, out, nullptr, NTOK, VV, DD, 0);
}

// ---------------- launcher ----------------
extern "C" void kernel_launch(void* const* d_in, const int* in_sizes, int n_in,
                              void* d_out, int out_size) {
    const int*   x     = (const int*)d_in[0];
    const float* embed = (const float*)d_in[1];
    const float* kpar  = (const float*)d_in[2];
    const float* gamma = (const float*)d_in[3];
    const float* beta  = (const float*)d_in[4];
    const float* W1    = (const float*)d_in[5];
    const float* b1    = (const float*)d_in[6];
    const float* W2    = (const float*)d_in[7];
    const float* b2    = (const float*)d_in[8];
    float* out = (float*)d_out;

    cudaFuncSetAttribute(gemm1_f16, cudaFuncAttributeMaxDynamicSharedMemorySize, GSMEM1);
    cudaFuncSetAttribute(gemm2_f16, cudaFuncAttributeMaxDynamicSharedMemorySize, GSMEM1);
    cudaFuncSetAttribute(gemm_out_f16, cudaFuncAttributeMaxDynamicSharedMemorySize, GSMEM2);
    cudaFuncSetAttribute(mag_ln_kernel, cudaFuncAttributeMaxDynamicSharedMemorySize, MLN_SMEM);

    dim3 sg(BB, NCH);
    dim3 sg2(BB, NCH, 2);

    embed_cumprod_kernel<<<NTOK / 8, 256>>>(x, embed);
    split_weights_kernel<<<(3 * DD * HH) / 256, 256>>>(W1, W2);
    embedT_split_kernel<<<dim3(VV / 32, DD / 32), dim3(32, 8)>>>(embed);
    boundA_kernel<<<sg2, 256>>>();
    boundB_kernel<<<BB, DD>>>();
    boundC_kernel<<<sg2, 256>>>();

    for (int l = 0; l < 3; l++) {
        scanA_kernel<<<sg2, 256>>>(kpar, l);
        scanB_kernel<<<BB, DD>>>(kpar, l);
        mag_ln_kernel<<<sg, DD, MLN_SMEM>>>(kpar, l, gamma + l * DD, beta + l * DD);
        gemm1_f16<<<dim3(HH / 128, NTOK / 128), 256, GSMEM1>>>(b1 + l * HH, l);
        gemm2_f16<<<dim3(DD / 128, NTOK / 128), 256, GSMEM1>>>(b2 + l * DD, l);
    }
    gemm_out_f16<<<dim3(VV / 128, NTOK / 128), 256, GSMEM2>>>(out);
}

// round 17
// speedup vs baseline: 1.0156x; 1.0156x over previous
#include <cuda_runtime.h>
#include <cuda_fp16.h>
#include <math.h>
#include <stdint.h>

#define BB 4
#define TT 2048
#define DD 512
#define HH 2048
#define VV 256
#define NTOK (BB*TT)   // 8192
#define CS 64
#define NCH (TT/CS)

// ---------------- scratch ----------------
__device__ __align__(128) float g_h[NTOK*DD];
__device__ __align__(128) float g_s1[NTOK*DD];
__device__ __align__(128) float g_partA[BB*NCH*DD];
__device__ __align__(128) float g_partB[BB*NCH*DD];
__device__ __align__(128) __half g_s2[NTOK*DD];                 // LN out, fp16
__device__ __align__(128) __half g_act[(size_t)NTOK*HH];        // GELU out, fp16
__device__ __align__(128) __half g_hq[NTOK*DD];                 // final h, fp16
__device__ __align__(128) __half g_w1h[3*DD*HH];
__device__ __align__(128) __half g_w2h[3*DD*HH];
__device__ __align__(128) __half g_eth[DD*VV];                  // embed^T hi
__device__ __align__(128) __half g_etl[DD*VV];                  // embed^T lo

__device__ __forceinline__ float softplus_lambda(float kv) {
    float sp = (kv > 0.f) ? (kv + log1pf(expf(-kv))) : log1pf(expf(kv));
    return expf(-sp);
}

// ---------------- weight prepass (both W1, W2 single fp16) -----------------
__global__ void split_weights_kernel(const float* __restrict__ W1, const float* __restrict__ W2) {
    size_t i = (size_t)blockIdx.x * blockDim.x + threadIdx.x;
    g_w1h[i] = __float2half(W1[i]);
    g_w2h[i] = __float2half(W2[i]);
}

// ---------------- embed^T split prepass: E[VV][DD] -> embT[DD][VV] hi/lo ---
__global__ void embedT_split_kernel(const float* __restrict__ E) {
    __shared__ float t[32][33];
    int v0 = blockIdx.x * 32, d0 = blockIdx.y * 32;
    #pragma unroll
    for (int i = threadIdx.y; i < 32; i += 8)
        t[i][threadIdx.x] = E[(size_t)(v0 + i) * DD + d0 + threadIdx.x];
    __syncthreads();
    #pragma unroll
    for (int i = threadIdx.y; i < 32; i += 8) {
        float val = t[threadIdx.x][i];
        size_t idx = (size_t)(d0 + i) * VV + v0 + threadIdx.x;
        __half hh = __float2half(val);
        g_eth[idx] = hh;
        g_etl[idx] = __float2half(val - __half2float(hh));
    }
}

// ---------------- fused embed gather + tanh(cumprod) (warp per token) ------
__global__ void embed_cumprod_kernel(const int* __restrict__ x, const float* __restrict__ embed) {
    int w = threadIdx.x >> 5;
    int lane = threadIdx.x & 31;
    int tok = blockIdx.x * 8 + w;
    const float* src = embed + (size_t)x[tok] * DD;
    size_t base = (size_t)tok * DD + lane * 16;
    float v[16];
    #pragma unroll
    for (int j = 0; j < 4; j++)
        *(float4*)&v[j * 4] = *(const float4*)(src + lane * 16 + j * 4);
    float c[16];
    float run = 1.f;
    #pragma unroll
    for (int j = 0; j < 16; j++) {
        run *= v[j];
        c[j] = run;
    }
    float incl = run;
    #pragma unroll
    for (int off = 1; off < 32; off <<= 1) {
        float p = __shfl_up_sync(0xffffffffu, incl, off);
        if (lane >= off) incl *= p;
    }
    float pre = __shfl_up_sync(0xffffffffu, incl, 1);
    if (lane == 0) pre = 1.f;
    #pragma unroll
    for (int j = 0; j < 4; j++) {
        *(float4*)&g_h[base + j * 4] = *(const float4*)&v[j * 4];
        float4 o;
        o.x = tanhf(pre * c[j * 4 + 0]);
        o.y = tanhf(pre * c[j * 4 + 1]);
        o.z = tanhf(pre * c[j * 4 + 2]);
        o.w = tanhf(pre * c[j * 4 + 3]);
        *(float4*)&g_s1[base + j * 4] = o;
    }
}

// ============= boundary scan (d-split: grid z=2, 256 threads) ==============
__global__ void boundA_kernel() {
    int b = blockIdx.x, ch = blockIdx.y;
    int d = blockIdx.z * 256 + threadIdx.x;
    size_t base = ((size_t)b * TT + ch * CS) * DD + d;
    float s = 0.f;
    #pragma unroll 8
    for (int i = 0; i < CS; i++) s += g_s1[base + (size_t)i * DD];
    g_partA[((size_t)b * NCH + ch) * DD + d] = s;
}

// widened: 2048 independent chains over 16 blocks x 128 threads
__global__ void boundB_kernel() {
    int id = blockIdx.x * 128 + threadIdx.x;
    int b = id >> 9, d = id & (DD - 1);
    float c = 0.f;
    for (int ch = 0; ch < NCH; ch++) {
        size_t idx = ((size_t)b * NCH + ch) * DD + d;
        float v = g_partA[idx];
        g_partA[idx] = c;
        c += v;
    }
}

__global__ void boundC_kernel() {
    int b = blockIdx.x, ch = blockIdx.y;
    int d = blockIdx.z * 256 + threadIdx.x;
    size_t base = ((size_t)b * TT + ch * CS) * DD + d;
    float acc = g_partA[((size_t)b * NCH + ch) * DD + d];
    #pragma unroll 4
    for (int i = 0; i < CS; i++) {
        size_t idx = base + (size_t)i * DD;
        acc += g_s1[idx];
        g_h[idx] = g_h[idx] * (1.0f + acc);
    }
}

// ============= per-layer scans =============================================
__global__ void scanA_kernel(const float* __restrict__ kpar, int l) {
    int b = blockIdx.x, ch = blockIdx.y;
    int d = blockIdx.z * 256 + threadIdx.x;
    float lam = softplus_lambda(kpar[l]);
    size_t base = ((size_t)b * TT + ch * CS) * DD + d;
    float s = 0.f, loc = 0.f;
    #pragma unroll 4
    for (int i = 0; i < CS; i++) {
        float v = g_h[base + (size_t)i * DD];
        s += v;
        loc = v + lam * loc;
    }
    size_t pidx = ((size_t)b * NCH + ch) * DD + d;
    g_partA[pidx] = s;
    g_partB[pidx] = loc;
}

// widened: 2048 independent chains over 16 blocks x 128 threads
__global__ void scanB_kernel(const float* __restrict__ kpar, int l) {
    int id = blockIdx.x * 128 + threadIdx.x;
    int b = id >> 9, d = id & (DD - 1);
    float lam = softplus_lambda(kpar[l]);
    float lamCS = powf(lam, (float)CS);
    float c1 = 0.f, c2 = 0.f;
    for (int ch = 0; ch < NCH; ch++) {
        size_t idx = ((size_t)b * NCH + ch) * DD + d;
        float a = g_partA[idx];
        float v = g_partB[idx];
        g_partA[idx] = c1;
        g_partB[idx] = c2;
        c1 += a;
        c2 = v + lamCS * c2;
    }
}

// ======== fused mag + decay-ctx + layernorm -> fp16 s2 =====================
#define MLN_SMEM ((CS*DD + 3*CS*17 + 3*CS) * 4)

__global__ void __launch_bounds__(DD, 1) mag_ln_kernel(const float* __restrict__ kpar, int l,
                                                       const float* __restrict__ gamma,
                                                       const float* __restrict__ beta) {
    extern __shared__ float sm[];
    float* sS  = sm;
    float* aM  = sS + CS * DD;
    float* a1  = aM + CS * 17;
    float* a2  = a1 + CS * 17;
    float* smu = a2 + CS * 17;
    float* srs = smu + CS;
    float* smg = srs + CS;

    int b = blockIdx.x, ch = blockIdx.y;
    int d = threadIdx.x;
    int lane = d & 31, wd = d >> 5;
    int t0 = ch * CS;
    size_t base = ((size_t)b * TT + t0) * DD + d;
    float lam = softplus_lambda(kpar[l]);
    float acc = g_partA[((size_t)b * NCH + ch) * DD + d];
    float S = g_partB[((size_t)b * NCH + ch) * DD + d];
    float hp = (t0 > 0) ? g_h[base - DD] : 0.f;

    #pragma unroll 4
    for (int i = 0; i < CS; i++) {
        float v = g_h[base + (size_t)i * DD];
        acc += v;
        float diff = acc - hp;
        float sq = diff * diff;
        S = v + lam * S;
        sS[i * DD + d] = S;
        float u1 = fabsf(S);
        float u2 = S * S;
        #pragma unroll
        for (int o = 16; o; o >>= 1) {
            sq += __shfl_down_sync(0xffffffffu, sq, o);
            u1 += __shfl_down_sync(0xffffffffu, u1, o);
            u2 += __shfl_down_sync(0xffffffffu, u2, o);
        }
        if (lane == 0) {
            aM[i * 17 + wd] = sq;
            a1[i * 17 + wd] = u1;
            a2[i * 17 + wd] = u2;
        }
        hp = v;
    }
    __syncthreads();
    if (d < CS) {
        float sm_ = 0.f, s1_ = 0.f, s2_ = 0.f;
        #pragma unroll
        for (int w = 0; w < 16; w++) {
            sm_ += aM[d * 17 + w];
            s1_ += a1[d * 17 + w];
            s2_ += a2[d * 17 + w];
        }
        float mag = sqrtf(sm_);
        float mu = mag * s1_ * (1.0f / DD);
        float ex2 = mag * mag * s2_ * (1.0f / DD);
        float var = ex2 - mu * mu;
        smu[d] = mu;
        srs[d] = rsqrtf(var + 1e-3f);
        smg[d] = mag;
    }
    __syncthreads();
    float gm = gamma[d], bt = beta[d];
    #pragma unroll 4
    for (int i = 0; i < CS; i++) {
        float ctx = smg[i] * fabsf(sS[i * DD + d]);
        float y = (ctx - smu[i]) * srs[i] * gm + bt;
        g_s2[base + (size_t)i * DD] = __float2half(y);
    }
}

// ============ fp16 tensor-core GEMM, K32 stages (2 x K16 sub-tiles) ========
// EXACT R15 version (proven fastest): 128x128 tile, 8 warps, register staging,
// double-buffered, 2 CTAs/SM.
#define AROWB 48
#define A_TILE_B (128*AROWB)           // 6144 per K16
#define BROWB 272
#define B_TILE_B (16*BROWB)            // 4352 per K16
#define KSUB 2
#define A_STAGE (KSUB*A_TILE_B)        // 12288
#define B_STAGE (KSUB*2*B_TILE_B)      // 17408
#define SM_A_BYTES (2*A_STAGE)         // 24576
#define SM_B_BYTES (2*B_STAGE)         // 34816
#define GSMEM (SM_A_BYTES + SM_B_BYTES)  // 59392

#define LDSM4(r0,r1,r2,r3,addr) \
    asm volatile("ldmatrix.sync.aligned.m8n8.x4.shared.b16 {%0,%1,%2,%3},[%4];" \
                 : "=r"(r0),"=r"(r1),"=r"(r2),"=r"(r3) : "r"(addr))
#define LDSM4T(r0,r1,r2,r3,addr) \
    asm volatile("ldmatrix.sync.aligned.m8n8.x4.trans.shared.b16 {%0,%1,%2,%3},[%4];" \
                 : "=r"(r0),"=r"(r1),"=r"(r2),"=r"(r3) : "r"(addr))
#define MMA_F16(c,a,b0,b1) \
    asm volatile("mma.sync.aligned.m16n8k16.row.col.f32.f16.f16.f32 " \
                 "{%0,%1,%2,%3},{%4,%5,%6,%7},{%8,%9},{%0,%1,%2,%3};" \
                 : "+f"(c[0]),"+f"(c[1]),"+f"(c[2]),"+f"(c[3]) \
                 : "r"(a[0]),"r"(a[1]),"r"(a[2]),"r"(a[3]),"r"(b0),"r"(b1))

struct StageRegs2 { uint4 ah[KSUB], bh[KSUB], bl[KSUB]; };

template <int TERMS>
__device__ __forceinline__ void ldg_tile(const __half* __restrict__ A,
                                         const __half* __restrict__ Bh,
                                         const __half* __restrict__ Bl,
                                         int bm, int bn, int k0, int K, int N,
                                         int tid, StageRegs2& r) {
    int arow = tid >> 1, aseg = tid & 1;
    int k = tid >> 4, ng = tid & 15;
    #pragma unroll
    for (int s = 0; s < KSUB; s++) {
        int ks = k0 + s * 16;
        r.ah[s] = *(const uint4*)(A + (size_t)(bm + arow) * K + ks + aseg * 8);
        size_t bbase = (size_t)(ks + k) * N + bn + ng * 8;
        r.bh[s] = *(const uint4*)(Bh + bbase);
        if (TERMS == 2) r.bl[s] = *(const uint4*)(Bl + bbase);
    }
}

template <int TERMS>
__device__ __forceinline__ void sts_tile(char* sbase, int p, int tid, const StageRegs2& r) {
    int arow = tid >> 1, aseg = tid & 1;
    int k = tid >> 4, ng = tid & 15;
    #pragma unroll
    for (int s = 0; s < KSUB; s++) {
        *(uint4*)(sbase + p * A_STAGE + s * A_TILE_B + arow * AROWB + aseg * 16) = r.ah[s];
        char* Bp = sbase + SM_A_BYTES + p * B_STAGE + s * (2 * B_TILE_B);
        *(uint4*)(Bp + k * BROWB + ng * 16) = r.bh[s];
        if (TERMS == 2) *(uint4*)(Bp + B_TILE_B + k * BROWB + ng * 16) = r.bl[s];
    }
}

__device__ __forceinline__ float gelu_exact(float c) {
    return 0.5f * c * (1.0f + erff(c * 0.70710678118654752f));
}

template <int EPI, int TERMS>
__device__ __forceinline__ void gemm_f16(const __half* __restrict__ A,
                                         const __half* __restrict__ Bh,
                                         const __half* __restrict__ Bl,
                                         const float* __restrict__ bias,
                                         float* __restrict__ Cf,
                                         __half* __restrict__ Ch,
                                         int M, int N, int K, int emit_half) {
    extern __shared__ char smc[];
    const int bm = blockIdx.y * 128;
    const int bn = blockIdx.x * 128;
    const int tid = threadIdx.x;
    const int lane = tid & 31;
    const int wid = tid >> 5;
    const int wm = wid >> 2, wn = wid & 3;
    const int g = lane >> 2, kq = lane & 3;
    const int lrow = lane & 7, lmat = lane >> 3;

    const uint32_t smem_u32 = (uint32_t)__cvta_generic_to_shared(smc);
    const uint32_t aoff = smem_u32 + (uint32_t)((wm * 64 + (lmat & 1) * 8 + lrow) * AROWB + (lmat >> 1) * 16);
    const uint32_t boff = smem_u32 + SM_A_BYTES +
                          (uint32_t)(((lmat & 1) * 8 + lrow) * BROWB + (wn * 32 + (lmat >> 1) * 8) * 2);

    float acc[4][4][4];
    #pragma unroll
    for (int mt = 0; mt < 4; mt++)
        #pragma unroll
        for (int nt = 0; nt < 4; nt++)
            #pragma unroll
            for (int r = 0; r < 4; r++) acc[mt][nt][r] = 0.f;

    const int KT = K >> 5;             // K32 stages
    StageRegs2 sr;
    ldg_tile<TERMS>(A, Bh, Bl, bm, bn, 0, K, N, tid, sr);
    sts_tile<TERMS>(smc, 0, tid, sr);
    __syncthreads();

    for (int kt = 0; kt < KT; kt++) {
        const int p = kt & 1;
        const bool more = (kt + 1 < KT);
        if (more) ldg_tile<TERMS>(A, Bh, Bl, bm, bn, (kt + 1) << 5, K, N, tid, sr);

        #pragma unroll
        for (int s = 0; s < KSUB; s++) {
            const uint32_t aB = aoff + p * A_STAGE + s * A_TILE_B;
            const uint32_t bB = boff + p * B_STAGE + s * (2 * B_TILE_B);
            uint32_t aH[4][4];
            #pragma unroll
            for (int mt = 0; mt < 4; mt++)
                LDSM4(aH[mt][0], aH[mt][1], aH[mt][2], aH[mt][3], aB + mt * (16 * AROWB));
            #pragma unroll
            for (int ntp = 0; ntp < 2; ntp++) {
                uint32_t bh[4];
                LDSM4T(bh[0], bh[1], bh[2], bh[3], bB + ntp * 32);
                if (TERMS == 2) {
                    uint32_t bl[4];
                    LDSM4T(bl[0], bl[1], bl[2], bl[3], bB + ntp * 32 + B_TILE_B);
                    #pragma unroll
                    for (int w = 0; w < 2; w++) {
                        const int nt = 2 * ntp + w;
                        #pragma unroll
                        for (int mt = 0; mt < 4; mt++) {
                            MMA_F16(acc[mt][nt], aH[mt], bl[2 * w], bl[2 * w + 1]);
                            MMA_F16(acc[mt][nt], aH[mt], bh[2 * w], bh[2 * w + 1]);
                        }
                    }
                } else {
                    #pragma unroll
                    for (int w = 0; w < 2; w++) {
                        const int nt = 2 * ntp + w;
                        #pragma unroll
                        for (int mt = 0; mt < 4; mt++)
                            MMA_F16(acc[mt][nt], aH[mt], bh[2 * w], bh[2 * w + 1]);
                    }
                }
            }
        }
        if (more) sts_tile<TERMS>(smc, p ^ 1, tid, sr);
        __syncthreads();
    }

    // epilogue
    #pragma unroll
    for (int mt = 0; mt < 4; mt++) {
        const int m0 = bm + wm * 64 + mt * 16 + g;
        #pragma unroll
        for (int nt = 0; nt < 4; nt++) {
            const int n0 = bn + wn * 32 + nt * 8 + kq * 2;
            const float b0 = (EPI == 2) ? 0.f : bias[n0];
            const float b1 = (EPI == 2) ? 0.f : bias[n0 + 1];
            if (EPI == 0) {
                float v0 = gelu_exact(acc[mt][nt][0] + b0);
                float v1 = gelu_exact(acc[mt][nt][1] + b1);
                float v2 = gelu_exact(acc[mt][nt][2] + b0);
                float v3 = gelu_exact(acc[mt][nt][3] + b1);
                __half2 p01 = __floats2half2_rn(v0, v1);
                __half2 p23 = __floats2half2_rn(v2, v3);
                size_t i0 = ((size_t)m0 * N + n0) >> 1;
                size_t i1 = ((size_t)(m0 + 8) * N + n0) >> 1;
                ((__half2*)Ch)[i0] = p01;
                ((__half2*)Ch)[i1] = p23;
            } else if (EPI == 1) {
                float2* p0 = (float2*)&Cf[(size_t)m0 * N + n0];
                float2* p1 = (float2*)&Cf[(size_t)(m0 + 8) * N + n0];
                float2 o0 = *p0, o1 = *p1;
                o0.x += acc[mt][nt][0] + b0;
                o0.y += acc[mt][nt][1] + b1;
                o1.x += acc[mt][nt][2] + b0;
                o1.y += acc[mt][nt][3] + b1;
                *p0 = o0;
                *p1 = o1;
                if (emit_half) {
                    size_t i0 = ((size_t)m0 * N + n0) >> 1;
                    size_t i1 = ((size_t)(m0 + 8) * N + n0) >> 1;
                    ((__half2*)Ch)[i0] = __floats2half2_rn(o0.x, o0.y);
                    ((__half2*)Ch)[i1] = __floats2half2_rn(o1.x, o1.y);
                }
            } else {
                *(float2*)&Cf[(size_t)m0 * N + n0] = make_float2(acc[mt][nt][0], acc[mt][nt][1]);
                *(float2*)&Cf[(size_t)(m0 + 8) * N + n0] = make_float2(acc[mt][nt][2], acc[mt][nt][3]);
            }
        }
    }
}

__global__ void __launch_bounds__(256, 2) gemm1_f16(const float* __restrict__ b1, int l) {
    gemm_f16<0, 1>(g_s2, g_w1h + (size_t)l * DD * HH, nullptr,
                   b1, nullptr, g_act, NTOK, HH, DD, 0);
}
__global__ void __launch_bounds__(256, 2) gemm2_f16(const float* __restrict__ b2, int l) {
    gemm_f16<1, 1>(g_act, g_w2h + (size_t)l * DD * HH, nullptr,
                   b2, g_h, g_hq, NTOK, DD, HH, l == 2 ? 1 : 0);
}
__global__ void __launch_bounds__(256, 2) gemm_out_f16(float* __restrict__ out) {
    gemm_f16<2, 2>(g_hq, g_eth, g_etl, nullptr, out, nullptr, NTOK, VV, DD, 0);
}

// ---------------- launcher ----------------
extern "C" void kernel_launch(void* const* d_in, const int* in_sizes, int n_in,
                              void* d_out, int out_size) {
    const int*   x     = (const int*)d_in[0];
    const float* embed = (const float*)d_in[1];
    const float* kpar  = (const float*)d_in[2];
    const float* gamma = (const float*)d_in[3];
    const float* beta  = (const float*)d_in[4];
    const float* W1    = (const float*)d_in[5];
    const float* b1    = (const float*)d_in[6];
    const float* W2    = (const float*)d_in[7];
    const float* b2    = (const float*)d_in[8];
    float* out = (float*)d_out;

    cudaFuncSetAttribute(gemm1_f16, cudaFuncAttributeMaxDynamicSharedMemorySize, GSMEM);
    cudaFuncSetAttribute(gemm2_f16, cudaFuncAttributeMaxDynamicSharedMemorySize, GSMEM);
    cudaFuncSetAttribute(gemm_out_f16, cudaFuncAttributeMaxDynamicSharedMemorySize, GSMEM);
    cudaFuncSetAttribute(mag_ln_kernel, cudaFuncAttributeMaxDynamicSharedMemorySize, MLN_SMEM);

    dim3 sg(BB, NCH);
    dim3 sg2(BB, NCH, 2);

    embed_cumprod_kernel<<<NTOK / 8, 256>>>(x, embed);
    split_weights_kernel<<<(3 * DD * HH) / 256, 256>>>(W1, W2);
    embedT_split_kernel<<<dim3(VV / 32, DD / 32), dim3(32, 8)>>>(embed);
    boundA_kernel<<<sg2, 256>>>();
    boundB_kernel<<<16, 128>>>();
    boundC_kernel<<<sg2, 256>>>();

    for (int l = 0; l < 3; l++) {
        scanA_kernel<<<sg2, 256>>>(kpar, l);
        scanB_kernel<<<16, 128>>>(kpar, l);
        mag_ln_kernel<<<sg, DD, MLN_SMEM>>>(kpar, l, gamma + l * DD, beta + l * DD);
        gemm1_f16<<<dim3(HH / 128, NTOK / 128), 256, GSMEM>>>(b1 + l * HH, l);
        gemm2_f16<<<dim3(DD / 128, NTOK / 128), 256, GSMEM>>>(b2 + l * DD, l);
    }
    gemm_out_f16<<<dim3(VV / 128, NTOK / 128), 256, GSMEM>>>(out);
}